// round 1
// baseline (speedup 1.0000x reference)
#include <cuda_runtime.h>
#include <math.h>

#define Bmax 4
#define C_ 64
#define H_ 128
#define W_ 128
#define O_ 64
#define K_ 9
#define HW_ (H_*W_)

// scratch (allocation-free rule: __device__ globals)
__device__ float g_xn[Bmax*HW_*C_ + 16384];   // NHWC x, padded for clamped-corner overreads
__device__ float g_wt[K_*C_*O_];              // main weights  [k][c][o]
__device__ float g_omw[K_*C_*32];             // offset-conv weights [k][c][oc(padded 32)]

// ---------------- NCHW -> NHWC transpose ----------------
__global__ void k_transpose(const float* __restrict__ x) {
    __shared__ float t[32][33];
    int b  = blockIdx.z >> 1;
    int c0 = (blockIdx.z & 1) * 32;
    int h  = blockIdx.y;
    int w0 = blockIdx.x * 32;
    int tx = threadIdx.x, ty = threadIdx.y;
#pragma unroll
    for (int i = 0; i < 4; i++) {
        int c = c0 + ty + i*8;
        t[ty + i*8][tx] = x[((size_t)(b*C_ + c)*H_ + h)*W_ + w0 + tx];
    }
    __syncthreads();
#pragma unroll
    for (int i = 0; i < 4; i++) {
        int w = w0 + ty + i*8;
        g_xn[((size_t)(b*H_ + h)*W_ + w)*C_ + c0 + tx] = t[tx][ty + i*8];
    }
}

// ---------------- weight repack ----------------
__global__ void k_repack(const float* __restrict__ wgt, const float* __restrict__ omw) {
    int t = blockIdx.x*256 + threadIdx.x;
    if (t < K_*C_*O_) {
        int k = t / (C_*O_); int r = t % (C_*O_); int c = r >> 6; int o = r & 63;
        g_wt[t] = wgt[(o*C_ + c)*K_ + k];
    }
    if (t < K_*C_*32) {
        int k = t / (C_*32); int r = t % (C_*32); int c = r >> 5; int p = r & 31;
        g_omw[t] = (p < 27) ? omw[(p*C_ + c)*K_ + k] : 0.f;
    }
}

// ---------------- fused DCN: one block per (b, h) output row ----------------
__global__ __launch_bounds__(256, 2)
void k_dcn(const float* __restrict__ bias, const float* __restrict__ om_bias,
           float* __restrict__ out) {
    extern __shared__ float sm[];
    float4* s_w  = (float4*)sm;            // [9][128] bilinear corner weights (mask folded)
    float*  xs   = sm + 1152*4;            // [64][129] sampled/conv input tile val[c][px]
    float*  ws   = xs + 8256;              // [64][64] weight slice (phase1 uses [64][32])
    float*  om_s = ws + 4096;              // [32][128] offset-conv outputs
    int*    s_i0 = (int*)(om_s + 4096);    // [9][128] clamped base pixel index
    int*    s_d  = s_i0 + 1152;            // [9][128] packed (dyW<<16)|dx

    const int tid = threadIdx.x;
    const int h   = blockIdx.x;
    const int b   = blockIdx.y;
    const int pxq = tid & 31;              // px = pxq + 32*jj
    const float* xb = g_xn + (size_t)b*HW_*C_;

    // ---------- Phase 1: offset/mask conv (GEMM 32oc x 128px, Ktot=576) ----------
    float acc1[16];
#pragma unroll
    for (int i = 0; i < 16; i++) acc1[i] = 0.f;
    const int ocg = tid >> 5;              // oc = ocg*4 + ii

    for (int k = 0; k < K_; k++) {
        int ky = k / 3, kx = k - 3*ky;
        int yy = h + ky - 1;
        // stage input window val[c][px] (zero-padded)
        for (int e = tid; e < 2048; e += 256) {
            int c4 = e & 15, px = e >> 4;
            int xx = px + kx - 1;
            float4 v = make_float4(0.f, 0.f, 0.f, 0.f);
            if (yy >= 0 && yy < H_ && xx >= 0 && xx < W_)
                v = *(const float4*)(xb + ((size_t)yy*W_ + xx)*C_ + c4*4);
            int cb = c4*4;
            xs[cb*129 + px]     = v.x;
            xs[(cb+1)*129 + px] = v.y;
            xs[(cb+2)*129 + px] = v.z;
            xs[(cb+3)*129 + px] = v.w;
        }
        // stage weight slice [64c][32oc]
        {
            const float4* src = (const float4*)(g_omw + k*2048);
            for (int e = tid; e < 512; e += 256) ((float4*)ws)[e] = src[e];
        }
        __syncthreads();
#pragma unroll 4
        for (int c = 0; c < 64; c++) {
            float4 wv = *(float4*)(ws + c*32 + ocg*4);
            float wvv[4] = {wv.x, wv.y, wv.z, wv.w};
            float vvv[4];
            vvv[0] = xs[c*129 + pxq];
            vvv[1] = xs[c*129 + pxq + 32];
            vvv[2] = xs[c*129 + pxq + 64];
            vvv[3] = xs[c*129 + pxq + 96];
#pragma unroll
            for (int ii = 0; ii < 4; ii++)
#pragma unroll
                for (int jj = 0; jj < 4; jj++)
                    acc1[ii*4+jj] = fmaf(wvv[ii], vvv[jj], acc1[ii*4+jj]);
        }
        __syncthreads();
    }

    // ---------- Phase 2a: om -> smem (+ bias) ----------
#pragma unroll
    for (int ii = 0; ii < 4; ii++) {
        int oc = ocg*4 + ii;
        float bv = (oc < 27) ? __ldg(om_bias + oc) : 0.f;
#pragma unroll
        for (int jj = 0; jj < 4; jj++)
            om_s[oc*128 + pxq + 32*jj] = acc1[ii*4+jj] + bv;
    }
    __syncthreads();

    // ---------- Phase 2b: bilinear sampling prep per (px, k) ----------
    for (int e = tid; e < 1152; e += 256) {
        int px = e & 127, k = e >> 7;
        int ky = k / 3, kx = k - 3*ky;
        float oy = om_s[k*128 + px];
        float ox = om_s[(9+k)*128 + px];
        float mz = om_s[(18+k)*128 + px];
        float mk = 1.f / (1.f + expf(-mz));
        float pyf = oy + (float)(h - 1 + ky);
        float pxf = ox + (float)(px - 1 + kx);
        float y0f = floorf(pyf), x0f = floorf(pxf);
        float ly = pyf - y0f, lx = pxf - x0f;
        int y0 = (int)y0f, x0 = (int)x0f;
        bool vy0 = (y0 >= 0)   & (y0 < H_);
        bool vy1 = (y0 >= -1)  & (y0 < H_-1);
        bool vx0 = (x0 >= 0)   & (x0 < W_);
        bool vx1 = (x0 >= -1)  & (x0 < W_-1);
        float w00 = (1.f-ly)*(1.f-lx)*mk * (float)(vy0 & vx0);
        float w01 = (1.f-ly)*lx*mk       * (float)(vy0 & vx1);
        float w10 = ly*(1.f-lx)*mk       * (float)(vy1 & vx0);
        float w11 = ly*lx*mk             * (float)(vy1 & vx1);
        int cy0 = min(max(y0, 0), H_-1),   cx0 = min(max(x0, 0), W_-1);
        int cy1 = min(max(y0+1, 0), H_-1), cx1 = min(max(x0+1, 0), W_-1);
        s_w[e]  = make_float4(w00, w01, w10, w11);
        s_i0[e] = cy0*W_ + cx0;
        s_d[e]  = (cx1 - cx0) | (((cy1 - cy0)*W_) << 16);
    }
    __syncthreads();

    // ---------- Phase 3: main DCN GEMM (64o x 128px, Ktot=576) ----------
    float acc[32];
#pragma unroll
    for (int i = 0; i < 32; i++) acc[i] = 0.f;
    const int og = tid >> 5;               // o = og*8 + ii

    for (int k = 0; k < K_; k++) {
        // sample val[c][px] via bilinear gather from NHWC x
        for (int e = tid; e < 2048; e += 256) {
            int c4 = e & 15, px = e >> 4;
            int se = k*128 + px;
            float4 wv = s_w[se];
            int i0 = s_i0[se];
            int d  = s_d[se];
            int dx  = d & 0xffff;
            int dyw = d >> 16;
            const float* p00 = xb + (size_t)i0*C_ + c4*4;
            float4 a  = *(const float4*)(p00);
            float4 bb = *(const float4*)(p00 + dx*C_);
            float4 cc = *(const float4*)(p00 + dyw*C_);
            float4 dd = *(const float4*)(p00 + (dyw+dx)*C_);
            float r0 = wv.x*a.x + wv.y*bb.x + wv.z*cc.x + wv.w*dd.x;
            float r1 = wv.x*a.y + wv.y*bb.y + wv.z*cc.y + wv.w*dd.y;
            float r2 = wv.x*a.z + wv.y*bb.z + wv.z*cc.z + wv.w*dd.z;
            float r3 = wv.x*a.w + wv.y*bb.w + wv.z*cc.w + wv.w*dd.w;
            int cb = c4*4;
            xs[cb*129 + px]     = r0;
            xs[(cb+1)*129 + px] = r1;
            xs[(cb+2)*129 + px] = r2;
            xs[(cb+3)*129 + px] = r3;
        }
        // stage weight slice [64c][64o]
        {
            const float4* src = (const float4*)(g_wt + k*4096);
            for (int e = tid; e < 1024; e += 256) ((float4*)ws)[e] = src[e];
        }
        __syncthreads();
#pragma unroll 4
        for (int c = 0; c < 64; c++) {
            float4 wa = *(float4*)(ws + c*64 + og*8);
            float4 wb = *(float4*)(ws + c*64 + og*8 + 4);
            float wvv[8] = {wa.x, wa.y, wa.z, wa.w, wb.x, wb.y, wb.z, wb.w};
            float vvv[4];
            vvv[0] = xs[c*129 + pxq];
            vvv[1] = xs[c*129 + pxq + 32];
            vvv[2] = xs[c*129 + pxq + 64];
            vvv[3] = xs[c*129 + pxq + 96];
#pragma unroll
            for (int ii = 0; ii < 8; ii++)
#pragma unroll
                for (int jj = 0; jj < 4; jj++)
                    acc[ii*4+jj] = fmaf(wvv[ii], vvv[jj], acc[ii*4+jj]);
        }
        __syncthreads();
    }

    // ---------- Epilogue: NCHW store + bias ----------
#pragma unroll
    for (int ii = 0; ii < 8; ii++) {
        int o = og*8 + ii;
        float bv = __ldg(bias + o);
#pragma unroll
        for (int jj = 0; jj < 4; jj++)
            out[(((size_t)b*O_ + o)*H_ + h)*W_ + pxq + 32*jj] = acc[ii*4+jj] + bv;
    }
}

extern "C" void kernel_launch(void* const* d_in, const int* in_sizes, int n_in,
                              void* d_out, int out_size) {
    const float* x         = (const float*)d_in[0];
    const float* weight    = (const float*)d_in[1];
    const float* bias      = (const float*)d_in[2];
    const float* om_weight = (const float*)d_in[3];
    const float* om_bias   = (const float*)d_in[4];
    float* out = (float*)d_out;

    int B = in_sizes[0] / (C_*H_*W_);
    if (B < 1) B = 1;
    if (B > Bmax) B = Bmax;

    const int smem = 93440;
    cudaFuncSetAttribute(k_dcn, cudaFuncAttributeMaxDynamicSharedMemorySize, smem);

    k_transpose<<<dim3(W_/32, H_, B*2), dim3(32, 8)>>>(x);
    k_repack<<<(K_*C_*O_ + 255)/256, 256>>>(weight, om_weight);
    k_dcn<<<dim3(H_, B), 256, smem>>>(bias, om_bias, out);
}

// round 2
// speedup vs baseline: 1.0227x; 1.0227x over previous
#include <cuda_runtime.h>
#include <math.h>

#define Bmax 4
#define C_ 64
#define H_ 128
#define W_ 128
#define O_ 64
#define K_ 9
#define HW_ (H_*W_)

typedef unsigned long long ull;

__device__ __forceinline__ void fma2(ull &d, ull a, ull b) {
    asm("fma.rn.f32x2 %0, %1, %2, %0;" : "+l"(d) : "l"(a), "l"(b));
}
__device__ __forceinline__ ull pack2(float lo, float hi) {
    ull r;
    asm("mov.b64 %0, {%1, %2};" : "=l"(r) : "f"(lo), "f"(hi));
    return r;
}
__device__ __forceinline__ void unpack2(ull v, float &lo, float &hi) {
    asm("mov.b64 {%0, %1}, %2;" : "=f"(lo), "=f"(hi) : "l"(v));
}

// scratch (allocation-free rule: __device__ globals)
__device__ float g_xn[Bmax*HW_*C_ + 16384];   // NHWC x, padded for clamped-corner overreads
__device__ float g_wt[K_*C_*O_];              // main weights  [k][c][o]
__device__ float g_omw[K_*C_*32];             // offset-conv weights [k][c][oc(padded 32)]

// ---------------- NCHW -> NHWC transpose ----------------
__global__ void k_transpose(const float* __restrict__ x) {
    __shared__ float t[32][33];
    int b  = blockIdx.z >> 1;
    int c0 = (blockIdx.z & 1) * 32;
    int h  = blockIdx.y;
    int w0 = blockIdx.x * 32;
    int tx = threadIdx.x, ty = threadIdx.y;
#pragma unroll
    for (int i = 0; i < 4; i++) {
        int c = c0 + ty + i*8;
        t[ty + i*8][tx] = x[((size_t)(b*C_ + c)*H_ + h)*W_ + w0 + tx];
    }
    __syncthreads();
#pragma unroll
    for (int i = 0; i < 4; i++) {
        int w = w0 + ty + i*8;
        g_xn[((size_t)(b*H_ + h)*W_ + w)*C_ + c0 + tx] = t[tx][ty + i*8];
    }
}

// ---------------- weight repack ----------------
__global__ void k_repack(const float* __restrict__ wgt, const float* __restrict__ omw) {
    int t = blockIdx.x*256 + threadIdx.x;
    if (t < K_*C_*O_) {
        int k = t / (C_*O_); int r = t % (C_*O_); int c = r >> 6; int o = r & 63;
        g_wt[t] = wgt[(o*C_ + c)*K_ + k];
    }
    if (t < K_*C_*32) {
        int k = t / (C_*32); int r = t % (C_*32); int c = r >> 5; int p = r & 31;
        g_omw[t] = (p < 27) ? omw[(p*C_ + c)*K_ + k] : 0.f;
    }
}

// ---------------- fused DCN: one block per (b, h) output row ----------------
__global__ __launch_bounds__(256, 2)
void k_dcn(const float* __restrict__ bias, const float* __restrict__ om_bias,
           float* __restrict__ out) {
    extern __shared__ float sm[];
    float4* s_w  = (float4*)sm;            // [9][128] bilinear corner weights (mask folded)
    float*  xs   = sm + 1152*4;            // [64][129] sampled/conv input tile val[c][px]
    float*  ws   = xs + 8256;              // [64][64] weight slice (phase1 uses [64][32])
    float*  om_s = ws + 4096;              // [32][128] offset-conv outputs
    int*    s_i0 = (int*)(om_s + 4096);    // [9][128] clamped base pixel index
    int*    s_d  = s_i0 + 1152;            // [9][128] packed (dyW<<16)|dx

    const int tid = threadIdx.x;
    const int h   = blockIdx.x;
    const int b   = blockIdx.y;
    const int pxq = tid & 31;              // px = pxq + 32*jj
    const float* xb = g_xn + (size_t)b*HW_*C_;

    // ---------- Phase 1: offset/mask conv (GEMM 32oc x 128px, Ktot=576) ----------
    ull acc1[8];                           // [ocpair p(2)][jj(4)]
#pragma unroll
    for (int i = 0; i < 8; i++) acc1[i] = 0ULL;
    const int ocg = tid >> 5;              // oc = ocg*4 + {0..3}

    for (int k = 0; k < K_; k++) {
        int ky = k / 3, kx = k - 3*ky;
        int yy = h + ky - 1;
        // stage input window val[c][px] (zero-padded)
        for (int e = tid; e < 2048; e += 256) {
            int c4 = e & 15, px = e >> 4;
            int xx = px + kx - 1;
            float4 v = make_float4(0.f, 0.f, 0.f, 0.f);
            if (yy >= 0 && yy < H_ && xx >= 0 && xx < W_)
                v = *(const float4*)(xb + ((size_t)yy*W_ + xx)*C_ + c4*4);
            int cb = c4*4;
            xs[cb*129 + px]     = v.x;
            xs[(cb+1)*129 + px] = v.y;
            xs[(cb+2)*129 + px] = v.z;
            xs[(cb+3)*129 + px] = v.w;
        }
        // stage weight slice [64c][32oc]
        {
            const float4* src = (const float4*)(g_omw + k*2048);
            for (int e = tid; e < 512; e += 256) ((float4*)ws)[e] = src[e];
        }
        __syncthreads();
#pragma unroll 4
        for (int c = 0; c < 64; c++) {
            ull wp0 = *(const ull*)(ws + c*32 + ocg*4);
            ull wp1 = *(const ull*)(ws + c*32 + ocg*4 + 2);
            ull vb[4];
            vb[0] = pack2(xs[c*129 + pxq],      xs[c*129 + pxq]);
            vb[1] = pack2(xs[c*129 + pxq + 32], xs[c*129 + pxq + 32]);
            vb[2] = pack2(xs[c*129 + pxq + 64], xs[c*129 + pxq + 64]);
            vb[3] = pack2(xs[c*129 + pxq + 96], xs[c*129 + pxq + 96]);
#pragma unroll
            for (int jj = 0; jj < 4; jj++) { fma2(acc1[jj], wp0, vb[jj]); fma2(acc1[4+jj], wp1, vb[jj]); }
        }
        __syncthreads();
    }

    // ---------- Phase 2a: om -> smem (+ bias) ----------
#pragma unroll
    for (int p = 0; p < 2; p++) {
        int oc0 = ocg*4 + 2*p;
        float bv0 = (oc0   < 27) ? __ldg(om_bias + oc0)     : 0.f;
        float bv1 = (oc0+1 < 27) ? __ldg(om_bias + oc0 + 1) : 0.f;
#pragma unroll
        for (int jj = 0; jj < 4; jj++) {
            float lo, hi; unpack2(acc1[p*4 + jj], lo, hi);
            om_s[oc0*128     + pxq + 32*jj] = lo + bv0;
            om_s[(oc0+1)*128 + pxq + 32*jj] = hi + bv1;
        }
    }
    __syncthreads();

    // ---------- Phase 2b: bilinear sampling prep per (px, k) ----------
    for (int e = tid; e < 1152; e += 256) {
        int px = e & 127, k = e >> 7;
        int ky = k / 3, kx = k - 3*ky;
        float oy = om_s[k*128 + px];
        float ox = om_s[(9+k)*128 + px];
        float mz = om_s[(18+k)*128 + px];
        float mk = 1.f / (1.f + expf(-mz));
        float pyf = oy + (float)(h - 1 + ky);
        float pxf = ox + (float)(px - 1 + kx);
        float y0f = floorf(pyf), x0f = floorf(pxf);
        float ly = pyf - y0f, lx = pxf - x0f;
        int y0 = (int)y0f, x0 = (int)x0f;
        bool vy0 = (y0 >= 0)   & (y0 < H_);
        bool vy1 = (y0 >= -1)  & (y0 < H_-1);
        bool vx0 = (x0 >= 0)   & (x0 < W_);
        bool vx1 = (x0 >= -1)  & (x0 < W_-1);
        float w00 = (1.f-ly)*(1.f-lx)*mk * (float)(vy0 & vx0);
        float w01 = (1.f-ly)*lx*mk       * (float)(vy0 & vx1);
        float w10 = ly*(1.f-lx)*mk       * (float)(vy1 & vx0);
        float w11 = ly*lx*mk             * (float)(vy1 & vx1);
        int cy0 = min(max(y0, 0), H_-1),   cx0 = min(max(x0, 0), W_-1);
        int cy1 = min(max(y0+1, 0), H_-1), cx1 = min(max(x0+1, 0), W_-1);
        s_w[e]  = make_float4(w00, w01, w10, w11);
        s_i0[e] = cy0*W_ + cx0;
        s_d[e]  = (cx1 - cx0) | (((cy1 - cy0)*W_) << 16);
    }
    __syncthreads();

    // ---------- Phase 3: main DCN GEMM (64o x 128px, Ktot=576) ----------
    ull acc[16];                           // [opair p(4)][jj(4)]
#pragma unroll
    for (int i = 0; i < 16; i++) acc[i] = 0ULL;
    const int og = tid >> 5;               // o = og*8 + {0..7}

    for (int k = 0; k < K_; k++) {
        // sample val[c][px] via bilinear gather from NHWC x
        for (int e = tid; e < 2048; e += 256) {
            int c4 = e & 15, px = e >> 4;
            int se = k*128 + px;
            float4 wv = s_w[se];
            int i0 = s_i0[se];
            int d  = s_d[se];
            int dx  = d & 0xffff;
            int dyw = d >> 16;
            const float* p00 = xb + (size_t)i0*C_ + c4*4;
            float4 a  = *(const float4*)(p00);
            float4 bb = *(const float4*)(p00 + dx*C_);
            float4 cc = *(const float4*)(p00 + dyw*C_);
            float4 dd = *(const float4*)(p00 + (dyw+dx)*C_);
            float r0 = wv.x*a.x + wv.y*bb.x + wv.z*cc.x + wv.w*dd.x;
            float r1 = wv.x*a.y + wv.y*bb.y + wv.z*cc.y + wv.w*dd.y;
            float r2 = wv.x*a.z + wv.y*bb.z + wv.z*cc.z + wv.w*dd.z;
            float r3 = wv.x*a.w + wv.y*bb.w + wv.z*cc.w + wv.w*dd.w;
            int cb = c4*4;
            xs[cb*129 + px]     = r0;
            xs[(cb+1)*129 + px] = r1;
            xs[(cb+2)*129 + px] = r2;
            xs[(cb+3)*129 + px] = r3;
        }
        // stage weight slice [64c][64o]
        {
            const float4* src = (const float4*)(g_wt + k*4096);
            for (int e = tid; e < 1024; e += 256) ((float4*)ws)[e] = src[e];
        }
        __syncthreads();
#pragma unroll 4
        for (int c = 0; c < 64; c++) {
            ull wp[4];
#pragma unroll
            for (int p = 0; p < 4; p++) wp[p] = *(const ull*)(ws + c*64 + og*8 + 2*p);
            ull vb[4];
            vb[0] = pack2(xs[c*129 + pxq],      xs[c*129 + pxq]);
            vb[1] = pack2(xs[c*129 + pxq + 32], xs[c*129 + pxq + 32]);
            vb[2] = pack2(xs[c*129 + pxq + 64], xs[c*129 + pxq + 64]);
            vb[3] = pack2(xs[c*129 + pxq + 96], xs[c*129 + pxq + 96]);
#pragma unroll
            for (int p = 0; p < 4; p++)
#pragma unroll
                for (int jj = 0; jj < 4; jj++)
                    fma2(acc[p*4 + jj], wp[p], vb[jj]);
        }
        __syncthreads();
    }

    // ---------- Epilogue: NCHW store + bias ----------
#pragma unroll
    for (int p = 0; p < 4; p++) {
        int o0 = og*8 + 2*p;
        float bv0 = __ldg(bias + o0);
        float bv1 = __ldg(bias + o0 + 1);
#pragma unroll
        for (int jj = 0; jj < 4; jj++) {
            float lo, hi; unpack2(acc[p*4 + jj], lo, hi);
            out[(((size_t)b*O_ + o0    )*H_ + h)*W_ + pxq + 32*jj] = lo + bv0;
            out[(((size_t)b*O_ + o0 + 1)*H_ + h)*W_ + pxq + 32*jj] = hi + bv1;
        }
    }
}

extern "C" void kernel_launch(void* const* d_in, const int* in_sizes, int n_in,
                              void* d_out, int out_size) {
    const float* x         = (const float*)d_in[0];
    const float* weight    = (const float*)d_in[1];
    const float* bias      = (const float*)d_in[2];
    const float* om_weight = (const float*)d_in[3];
    const float* om_bias   = (const float*)d_in[4];
    float* out = (float*)d_out;

    int B = in_sizes[0] / (C_*H_*W_);
    if (B < 1) B = 1;
    if (B > Bmax) B = Bmax;

    const int smem = 93440;
    cudaFuncSetAttribute(k_dcn, cudaFuncAttributeMaxDynamicSharedMemorySize, smem);

    k_transpose<<<dim3(W_/32, H_, B*2), dim3(32, 8)>>>(x);
    k_repack<<<(K_*C_*O_ + 255)/256, 256>>>(weight, om_weight);
    k_dcn<<<dim3(H_, B), 256, smem>>>(bias, om_bias, out);
}

// round 5
// speedup vs baseline: 1.9785x; 1.9345x over previous
#include <cuda_runtime.h>
#include <math.h>
#include <stdint.h>

#define Bmax 4
#define C_ 64
#define H_ 128
#define W_ 128
#define O_ 64
#define K_ 9
#define HW_ (H_*W_)

__device__ __forceinline__ float to_tf32(float v) {
    float r; asm("cvt.rna.tf32.f32 %0, %1;" : "=f"(r) : "f"(v)); return r;
}
__device__ __forceinline__ void mma8(float4 &d, uint32_t a0, uint32_t a1, uint32_t a2, uint32_t a3,
                                     uint32_t b0, uint32_t b1) {
    asm("mma.sync.aligned.m16n8k8.row.col.f32.tf32.tf32.f32 "
        "{%0,%1,%2,%3},{%4,%5,%6,%7},{%8,%9},{%0,%1,%2,%3};"
        : "+f"(d.x), "+f"(d.y), "+f"(d.z), "+f"(d.w)
        : "r"(a0), "r"(a1), "r"(a2), "r"(a3), "r"(b0), "r"(b1));
}

// ---------------- device scratch ----------------
__device__ float g_xn[Bmax*HW_*C_ + 16384];   // NHWC x (fp32), padded
// B fragments, per-thread order:
// g_wt3: [k][ks(8)][j4(4)][t(32)] x float4 = (b0 j=2j4, b1 j=2j4, b0 j=2j4+1, b1 j=2j4+1)
__device__ float g_wt3[K_*8*4*32*4];
// g_w1:  [k][ks(8)][j4(2)][t(32)] x float4
__device__ float g_w1[K_*8*2*32*4];

// ---------------- NCHW -> NHWC transpose ----------------
__global__ void k_transpose(const float* __restrict__ x) {
    __shared__ float t[32][33];
    int b  = blockIdx.z >> 1;
    int c0 = (blockIdx.z & 1) * 32;
    int h  = blockIdx.y;
    int w0 = blockIdx.x * 32;
    int tx = threadIdx.x, ty = threadIdx.y;
#pragma unroll
    for (int i = 0; i < 4; i++) {
        int c = c0 + ty + i*8;
        t[ty + i*8][tx] = x[((size_t)(b*C_ + c)*H_ + h)*W_ + w0 + tx];
    }
    __syncthreads();
#pragma unroll
    for (int i = 0; i < 4; i++) {
        int w = w0 + ty + i*8;
        g_xn[((size_t)(b*H_ + h)*W_ + w)*C_ + c0 + tx] = t[tx][ty + i*8];
    }
}

// ---------------- weight repack into mma fragment order ----------------
__global__ void k_repack(const float* __restrict__ wgt, const float* __restrict__ omw) {
    int f = blockIdx.x*256 + threadIdx.x;
    if (f < K_*4096) {                    // main weights: 4096 floats per tap
        int q  = f & 3;
        int t  = (f >> 2) & 31;
        int j4 = (f >> 7) & 3;
        int ks = (f >> 9) & 7;
        int k  = f >> 12;
        int j  = 2*j4 + (q >> 1);
        int c  = ks*8 + (t & 3) + (q & 1)*4;
        int o  = j*8 + (t >> 2);
        g_wt3[f] = to_tf32(wgt[(o*C_ + c)*K_ + k]);
    } else if (f < K_*4096 + K_*2048) {   // om weights: 2048 floats per tap
        int f2 = f - K_*4096;
        int q  = f2 & 3;
        int t  = (f2 >> 2) & 31;
        int j4 = (f2 >> 7) & 1;
        int ks = (f2 >> 8) & 7;
        int k  = f2 >> 11;
        int j  = 2*j4 + (q >> 1);
        int c  = ks*8 + (t & 3) + (q & 1)*4;
        int oc = j*8 + (t >> 2);
        g_w1[f2] = (oc < 27) ? to_tf32(omw[(oc*C_ + c)*K_ + k]) : 0.f;
    }
}

// ---------------- fused DCN: one block per (b, h) output row ----------------
// smem byte layout
#define SM_XS  0        // 34816 B : A tile [128 px][68 c] fp32(tf32-rounded)
#define SM_B   34816    // 17408 B : union { B frags (16KB/8KB) , om_s [128][34] }
#define SM_SW  52224    // 18432 B : float4[9][128] corner weights
#define SM_I0  70656    // 4608  B : int[9][128]
#define SM_DD  75264    // 4608  B : int[9][128]
#define SM_TOT 79872

__global__ __launch_bounds__(256, 2)
void k_dcn(const float* __restrict__ bias, const float* __restrict__ om_bias,
           float* __restrict__ out) {
    extern __shared__ char sm[];
    float*  xs   = (float*)(sm + SM_XS);
    uint4*  bB   = (uint4*)(sm + SM_B);
    float*  om_s = (float*)(sm + SM_B);
    float4* s_w  = (float4*)(sm + SM_SW);
    int*    s_i0 = (int*)(sm + SM_I0);
    int*    s_d  = (int*)(sm + SM_DD);

    const int tid  = threadIdx.x;
    const int lane = tid & 31;
    const int w    = tid >> 5;
    const int tg   = lane >> 2;           // group id (row within 8)
    const int tig  = lane & 3;            // thread in group
    const int h    = blockIdx.x;
    const int b    = blockIdx.y;
    const int row0 = w*16 + tg;           // A fragment rows: row0, row0+8
    const float* xb = g_xn + (size_t)b*HW_*C_;

    // ---------- Phase 1: offset/mask conv (128px x 32oc x 576) ----------
    float4 acc1[4];
#pragma unroll
    for (int j = 0; j < 4; j++) acc1[j] = make_float4(0.f, 0.f, 0.f, 0.f);

    for (int k = 0; k < K_; k++) {
        int ky = k / 3, kx = k - 3*ky;
        int yy = h + ky - 1;
        // stage A: window values (zero-padded), tf32-rounded, [px][68]
        for (int e = tid; e < 2048; e += 256) {
            int c4 = e & 15, px = e >> 4;
            int xx = px + kx - 1;
            float4 v = make_float4(0.f, 0.f, 0.f, 0.f);
            if (yy >= 0 && yy < H_ && xx >= 0 && xx < W_)
                v = *(const float4*)(xb + ((size_t)yy*W_ + xx)*C_ + c4*4);
            v.x = to_tf32(v.x); v.y = to_tf32(v.y); v.z = to_tf32(v.z); v.w = to_tf32(v.w);
            *(float4*)(xs + px*68 + c4*4) = v;
        }
        // stage B frags: 512 float4
        {
            const uint4* src = (const uint4*)(g_w1 + k*2048);
            for (int e = tid; e < 512; e += 256) bB[e] = src[e];
        }
        __syncthreads();
#pragma unroll
        for (int ks = 0; ks < 8; ks++) {
            uint32_t a0 = __float_as_uint(xs[row0*68     + ks*8 + tig]);
            uint32_t a1 = __float_as_uint(xs[(row0+8)*68 + ks*8 + tig]);
            uint32_t a2 = __float_as_uint(xs[row0*68     + ks*8 + tig + 4]);
            uint32_t a3 = __float_as_uint(xs[(row0+8)*68 + ks*8 + tig + 4]);
            uint4 bf0 = bB[(ks*2 + 0)*32 + lane];
            uint4 bf1 = bB[(ks*2 + 1)*32 + lane];
            mma8(acc1[0], a0, a1, a2, a3, bf0.x, bf0.y);
            mma8(acc1[1], a0, a1, a2, a3, bf0.z, bf0.w);
            mma8(acc1[2], a0, a1, a2, a3, bf1.x, bf1.y);
            mma8(acc1[3], a0, a1, a2, a3, bf1.z, bf1.w);
        }
        __syncthreads();
    }

    // ---------- Phase 2a: write om fragments to smem [px][34] ----------
#pragma unroll
    for (int j = 0; j < 4; j++) {
        int col = j*8 + tig*2;
        *(float2*)(om_s + row0*34 + col)     = make_float2(acc1[j].x, acc1[j].y);
        *(float2*)(om_s + (row0+8)*34 + col) = make_float2(acc1[j].z, acc1[j].w);
    }
    __syncthreads();

    // ---------- Phase 2b: bilinear sampling prep per (px, k) ----------
    for (int e = tid; e < 1152; e += 256) {
        int px = e & 127, k = e >> 7;
        int ky = k / 3, kx = k - 3*ky;
        float oy = om_s[px*34 + k]      + __ldg(om_bias + k);
        float ox = om_s[px*34 + 9 + k]  + __ldg(om_bias + 9 + k);
        float mz = om_s[px*34 + 18 + k] + __ldg(om_bias + 18 + k);
        float mk = 1.f / (1.f + expf(-mz));
        float pyf = oy + (float)(h - 1 + ky);
        float pxf = ox + (float)(px - 1 + kx);
        float y0f = floorf(pyf), x0f = floorf(pxf);
        float ly = pyf - y0f, lx = pxf - x0f;
        int y0 = (int)y0f, x0 = (int)x0f;
        bool vy0 = (y0 >= 0)   & (y0 < H_);
        bool vy1 = (y0 >= -1)  & (y0 < H_-1);
        bool vx0 = (x0 >= 0)   & (x0 < W_);
        bool vx1 = (x0 >= -1)  & (x0 < W_-1);
        float w00 = (1.f-ly)*(1.f-lx)*mk * (float)(vy0 & vx0);
        float w01 = (1.f-ly)*lx*mk       * (float)(vy0 & vx1);
        float w10 = ly*(1.f-lx)*mk       * (float)(vy1 & vx0);
        float w11 = ly*lx*mk             * (float)(vy1 & vx1);
        int cy0 = min(max(y0, 0), H_-1),   cx0 = min(max(x0, 0), W_-1);
        int cy1 = min(max(y0+1, 0), H_-1), cx1 = min(max(x0+1, 0), W_-1);
        s_w[e]  = make_float4(w00, w01, w10, w11);
        s_i0[e] = cy0*W_ + cx0;
        s_d[e]  = (cx1 - cx0) | (((cy1 - cy0)*W_) << 16);
    }
    __syncthreads();

    // ---------- Phase 3: main DCN (128px x 64o x 576) ----------
    float4 acc[8];
#pragma unroll
    for (int j = 0; j < 8; j++) acc[j] = make_float4(0.f, 0.f, 0.f, 0.f);

    for (int k = 0; k < K_; k++) {
        // stage A: bilinear-sampled values
        for (int e = tid; e < 2048; e += 256) {
            int c4 = e & 15, px = e >> 4;
            int se = k*128 + px;
            float4 wv = s_w[se];
            int i0 = s_i0[se];
            int d  = s_d[se];
            int dx  = d & 0xffff;
            int dyw = d >> 16;
            const float* p00 = xb + (size_t)i0*C_ + c4*4;
            float4 a  = *(const float4*)(p00);
            float4 bb = *(const float4*)(p00 + dx*C_);
            float4 cc = *(const float4*)(p00 + dyw*C_);
            float4 dd = *(const float4*)(p00 + (dyw+dx)*C_);
            float4 r;
            r.x = to_tf32(wv.x*a.x + wv.y*bb.x + wv.z*cc.x + wv.w*dd.x);
            r.y = to_tf32(wv.x*a.y + wv.y*bb.y + wv.z*cc.y + wv.w*dd.y);
            r.z = to_tf32(wv.x*a.z + wv.y*bb.z + wv.z*cc.z + wv.w*dd.z);
            r.w = to_tf32(wv.x*a.w + wv.y*bb.w + wv.z*cc.w + wv.w*dd.w);
            *(float4*)(xs + px*68 + c4*4) = r;
        }
        // stage B frags: 1024 float4
        {
            const uint4* src = (const uint4*)(g_wt3 + k*4096);
            for (int e = tid; e < 1024; e += 256) bB[e] = src[e];
        }
        __syncthreads();
#pragma unroll
        for (int ks = 0; ks < 8; ks++) {
            uint32_t a0 = __float_as_uint(xs[row0*68     + ks*8 + tig]);
            uint32_t a1 = __float_as_uint(xs[(row0+8)*68 + ks*8 + tig]);
            uint32_t a2 = __float_as_uint(xs[row0*68     + ks*8 + tig + 4]);
            uint32_t a3 = __float_as_uint(xs[(row0+8)*68 + ks*8 + tig + 4]);
#pragma unroll
            for (int j4 = 0; j4 < 4; j4++) {
                uint4 bf = bB[(ks*4 + j4)*32 + lane];
                mma8(acc[j4*2],     a0, a1, a2, a3, bf.x, bf.y);
                mma8(acc[j4*2 + 1], a0, a1, a2, a3, bf.z, bf.w);
            }
        }
        __syncthreads();
    }

    // ---------- Epilogue: NCHW store + bias ----------
#pragma unroll
    for (int j = 0; j < 8; j++) {
        int o = j*8 + tig*2;
        float b0v = __ldg(bias + o);
        float b1v = __ldg(bias + o + 1);
        size_t base0 = (((size_t)b*O_ + o    )*H_ + h)*W_;
        size_t base1 = (((size_t)b*O_ + o + 1)*H_ + h)*W_;
        out[base0 + row0]     = acc[j].x + b0v;
        out[base1 + row0]     = acc[j].y + b1v;
        out[base0 + row0 + 8] = acc[j].z + b0v;
        out[base1 + row0 + 8] = acc[j].w + b1v;
    }
}

extern "C" void kernel_launch(void* const* d_in, const int* in_sizes, int n_in,
                              void* d_out, int out_size) {
    const float* x         = (const float*)d_in[0];
    const float* weight    = (const float*)d_in[1];
    const float* bias      = (const float*)d_in[2];
    const float* om_weight = (const float*)d_in[3];
    const float* om_bias   = (const float*)d_in[4];
    float* out = (float*)d_out;

    int B = in_sizes[0] / (C_*H_*W_);
    if (B < 1) B = 1;
    if (B > Bmax) B = Bmax;

    cudaFuncSetAttribute(k_dcn, cudaFuncAttributeMaxDynamicSharedMemorySize, SM_TOT);

    k_transpose<<<dim3(W_/32, H_, B*2), dim3(32, 8)>>>(x);
    int nrep = K_*4096 + K_*2048;
    k_repack<<<(nrep + 255)/256, 256>>>(weight, om_weight);
    k_dcn<<<dim3(H_, B), 256, SM_TOT>>>(bias, om_bias, out);
}

// round 6
// speedup vs baseline: 2.1194x; 1.0712x over previous
#include <cuda_runtime.h>
#include <math.h>
#include <stdint.h>

#define Bmax 4
#define C_ 64
#define H_ 128
#define W_ 128
#define O_ 64
#define K_ 9
#define HW_ (H_*W_)

typedef unsigned long long ull;

__device__ __forceinline__ float to_tf32(float v) {
    float r; asm("cvt.rna.tf32.f32 %0, %1;" : "=f"(r) : "f"(v)); return r;
}
__device__ __forceinline__ void mma8(float4 &d, uint32_t a0, uint32_t a1, uint32_t a2, uint32_t a3,
                                     uint32_t b0, uint32_t b1) {
    asm("mma.sync.aligned.m16n8k8.row.col.f32.tf32.tf32.f32 "
        "{%0,%1,%2,%3},{%4,%5,%6,%7},{%8,%9},{%0,%1,%2,%3};"
        : "+f"(d.x), "+f"(d.y), "+f"(d.z), "+f"(d.w)
        : "r"(a0), "r"(a1), "r"(a2), "r"(a3), "r"(b0), "r"(b1));
}
__device__ __forceinline__ ull pack2(float lo, float hi) {
    ull r; asm("mov.b64 %0, {%1, %2};" : "=l"(r) : "f"(lo), "f"(hi)); return r;
}
__device__ __forceinline__ ull mul2(ull a, ull b) {
    ull r; asm("mul.rn.f32x2 %0, %1, %2;" : "=l"(r) : "l"(a), "l"(b)); return r;
}
__device__ __forceinline__ ull fma2v(ull a, ull b, ull c) {
    ull r; asm("fma.rn.f32x2 %0, %1, %2, %3;" : "=l"(r) : "l"(a), "l"(b), "l"(c)); return r;
}

// ---------------- device scratch ----------------
__device__ float g_xn[Bmax*HW_*C_ + 16384];   // NHWC x (fp32), padded
// B fragments, per-thread order:
// g_wt3: [k][ks(8)][j4(4)][t(32)] x float4
__device__ float g_wt3[K_*8*4*32*4];
// g_w1:  [k][ks(8)][j4(2)][t(32)] x float4
__device__ float g_w1[K_*8*2*32*4];

// ---------------- NCHW -> NHWC transpose (vectorized) ----------------
__global__ void k_transpose(const float* __restrict__ x) {
    __shared__ float t[32][33];
    int b  = blockIdx.z >> 1;
    int c0 = (blockIdx.z & 1) * 32;
    int h  = blockIdx.y;
    int w0 = blockIdx.x * 32;
    int tid = threadIdx.x;
    int r  = tid >> 3;        // 0..31
    int q  = tid & 7;         // 0..7
    // read: c = c0+r, 4 w's
    float4 v = *(const float4*)(x + ((size_t)(b*C_ + c0 + r)*H_ + h)*W_ + w0 + q*4);
    t[r][q*4]     = v.x;
    t[r][q*4 + 1] = v.y;
    t[r][q*4 + 2] = v.z;
    t[r][q*4 + 3] = v.w;
    __syncthreads();
    // write: w = w0+r, 4 c's
    float4 o;
    o.x = t[q*4][r];
    o.y = t[q*4 + 1][r];
    o.z = t[q*4 + 2][r];
    o.w = t[q*4 + 3][r];
    *(float4*)(g_xn + ((size_t)(b*H_ + h)*W_ + w0 + r)*C_ + c0 + q*4) = o;
}

// ---------------- weight repack into mma fragment order ----------------
__global__ void k_repack(const float* __restrict__ wgt, const float* __restrict__ omw) {
    int f = blockIdx.x*256 + threadIdx.x;
    if (f < K_*4096) {                    // main weights
        int q  = f & 3;
        int t  = (f >> 2) & 31;
        int j4 = (f >> 7) & 3;
        int ks = (f >> 9) & 7;
        int k  = f >> 12;
        int j  = 2*j4 + (q >> 1);
        int c  = ks*8 + (t & 3) + (q & 1)*4;
        int o  = j*8 + (t >> 2);
        g_wt3[f] = to_tf32(wgt[(o*C_ + c)*K_ + k]);
    } else if (f < K_*4096 + K_*2048) {   // om weights
        int f2 = f - K_*4096;
        int q  = f2 & 3;
        int t  = (f2 >> 2) & 31;
        int j4 = (f2 >> 7) & 1;
        int ks = (f2 >> 8) & 7;
        int k  = f2 >> 11;
        int j  = 2*j4 + (q >> 1);
        int c  = ks*8 + (t & 3) + (q & 1)*4;
        int oc = j*8 + (t >> 2);
        g_w1[f2] = (oc < 27) ? to_tf32(omw[(oc*C_ + c)*K_ + k]) : 0.f;
    }
}

// ---------------- fused DCN: one block per (b, h) output row ----------------
// smem byte layout
#define SM_XS  0        // 35360 B : A tile [130 px][68 c]
#define SM_B   35360    // 24576 B : union { B frags (24KB ph1 / 16KB ph3), om_s [128][34] (17408) }
#define SM_SW  59936    // 18432 B : float4[9][128] corner weights
#define SM_I0  78368    // 4608  B : int[9][128]
#define SM_DD  82976    // 4608  B : int[9][128]
#define SM_TOT 87584

__global__ __launch_bounds__(256, 2)
void k_dcn(const float* __restrict__ bias, const float* __restrict__ om_bias,
           float* __restrict__ out) {
    extern __shared__ char sm[];
    float*  xs   = (float*)(sm + SM_XS);
    uint4*  bB   = (uint4*)(sm + SM_B);
    float*  om_s = (float*)(sm + SM_B);
    float4* s_w  = (float4*)(sm + SM_SW);
    int*    s_i0 = (int*)(sm + SM_I0);
    int*    s_d  = (int*)(sm + SM_DD);

    const int tid  = threadIdx.x;
    const int lane = tid & 31;
    const int w    = tid >> 5;
    const int tg   = lane >> 2;
    const int tig  = lane & 3;
    const int h    = blockIdx.x;
    const int b    = blockIdx.y;
    const int row0 = w*16 + tg;
    const float* xb = g_xn + (size_t)b*HW_*C_;

    // ---------- Phase 1: offset/mask conv (128px x 32oc x 576), 3 row-stagings ----------
    float4 acc1[4];
#pragma unroll
    for (int j = 0; j < 4; j++) acc1[j] = make_float4(0.f, 0.f, 0.f, 0.f);

    for (int ky = 0; ky < 3; ky++) {
        int yy = h + ky - 1;
        // stage input row: xs[r][c], r = xx+1, xx in [-1,128]
        for (int e = tid; e < 2080; e += 256) {
            int c4 = e & 15, r = e >> 4;
            int xx = r - 1;
            float4 v = make_float4(0.f, 0.f, 0.f, 0.f);
            if (yy >= 0 && yy < H_ && xx >= 0 && xx < W_)
                v = *(const float4*)(xb + ((size_t)yy*W_ + xx)*C_ + c4*4);
            *(float4*)(xs + r*68 + c4*4) = v;        // raw fp32; HMMA truncates to tf32
        }
        // stage B for 3 kx taps (contiguous in g_w1)
        {
            const uint4* src = (const uint4*)(g_w1 + (size_t)ky*3*2048);
            for (int e = tid; e < 1536; e += 256) bB[e] = src[e];
        }
        __syncthreads();
#pragma unroll
        for (int ks = 0; ks < 8; ks++) {
#pragma unroll
            for (int kx = 0; kx < 3; kx++) {
                int ra = (row0 + kx)*68 + ks*8 + tig;
                uint32_t a0 = __float_as_uint(xs[ra]);
                uint32_t a1 = __float_as_uint(xs[ra + 8*68]);
                uint32_t a2 = __float_as_uint(xs[ra + 4]);
                uint32_t a3 = __float_as_uint(xs[ra + 8*68 + 4]);
                uint4 bf0 = bB[kx*512 + (ks*2 + 0)*32 + lane];
                uint4 bf1 = bB[kx*512 + (ks*2 + 1)*32 + lane];
                mma8(acc1[0], a0, a1, a2, a3, bf0.x, bf0.y);
                mma8(acc1[1], a0, a1, a2, a3, bf0.z, bf0.w);
                mma8(acc1[2], a0, a1, a2, a3, bf1.x, bf1.y);
                mma8(acc1[3], a0, a1, a2, a3, bf1.z, bf1.w);
            }
        }
        __syncthreads();
    }

    // ---------- Phase 2a: write om fragments to smem [px][34] ----------
#pragma unroll
    for (int j = 0; j < 4; j++) {
        int col = j*8 + tig*2;
        *(float2*)(om_s + row0*34 + col)     = make_float2(acc1[j].x, acc1[j].y);
        *(float2*)(om_s + (row0+8)*34 + col) = make_float2(acc1[j].z, acc1[j].w);
    }
    __syncthreads();

    // ---------- Phase 2b: bilinear sampling prep per (px, k) ----------
    for (int e = tid; e < 1152; e += 256) {
        int px = e & 127, k = e >> 7;
        int ky = k / 3, kx = k - 3*ky;
        float oy = om_s[px*34 + k]      + __ldg(om_bias + k);
        float ox = om_s[px*34 + 9 + k]  + __ldg(om_bias + 9 + k);
        float mz = om_s[px*34 + 18 + k] + __ldg(om_bias + 18 + k);
        float mk = 1.f / (1.f + expf(-mz));
        float pyf = oy + (float)(h - 1 + ky);
        float pxf = ox + (float)(px - 1 + kx);
        float y0f = floorf(pyf), x0f = floorf(pxf);
        float ly = pyf - y0f, lx = pxf - x0f;
        int y0 = (int)y0f, x0 = (int)x0f;
        bool vy0 = (y0 >= 0)   & (y0 < H_);
        bool vy1 = (y0 >= -1)  & (y0 < H_-1);
        bool vx0 = (x0 >= 0)   & (x0 < W_);
        bool vx1 = (x0 >= -1)  & (x0 < W_-1);
        float w00 = (1.f-ly)*(1.f-lx)*mk * (float)(vy0 & vx0);
        float w01 = (1.f-ly)*lx*mk       * (float)(vy0 & vx1);
        float w10 = ly*(1.f-lx)*mk       * (float)(vy1 & vx0);
        float w11 = ly*lx*mk             * (float)(vy1 & vx1);
        int cy0 = min(max(y0, 0), H_-1),   cx0 = min(max(x0, 0), W_-1);
        int cy1 = min(max(y0+1, 0), H_-1), cx1 = min(max(x0+1, 0), W_-1);
        s_w[e]  = make_float4(w00, w01, w10, w11);
        s_i0[e] = cy0*W_ + cx0;
        s_d[e]  = (cx1 - cx0) | (((cy1 - cy0)*W_) << 16);
    }
    __syncthreads();

    // ---------- Phase 3: main DCN (128px x 64o x 576) ----------
    float4 acc[8];
#pragma unroll
    for (int j = 0; j < 8; j++) acc[j] = make_float4(0.f, 0.f, 0.f, 0.f);

    for (int k = 0; k < K_; k++) {
        // stage A: bilinear-sampled values (packed f32x2 math, no explicit tf32 cvt)
        for (int e = tid; e < 2048; e += 256) {
            int c4 = e & 15, px = e >> 4;
            int se = k*128 + px;
            float4 wv = s_w[se];
            int i0 = s_i0[se];
            int d  = s_d[se];
            int dx  = d & 0xffff;
            int dyw = d >> 16;
            const float* p00 = xb + (size_t)i0*C_ + c4*4;
            ulonglong2 A  = *(const ulonglong2*)(p00);
            ulonglong2 Bb = *(const ulonglong2*)(p00 + dx*C_);
            ulonglong2 Cc = *(const ulonglong2*)(p00 + dyw*C_);
            ulonglong2 Dd = *(const ulonglong2*)(p00 + (size_t)(dyw+dx)*C_);
            ull w00p = pack2(wv.x, wv.x);
            ull w01p = pack2(wv.y, wv.y);
            ull w10p = pack2(wv.z, wv.z);
            ull w11p = pack2(wv.w, wv.w);
            ull r0 = fma2v(w11p, Dd.x, fma2v(w10p, Cc.x, fma2v(w01p, Bb.x, mul2(w00p, A.x))));
            ull r1 = fma2v(w11p, Dd.y, fma2v(w10p, Cc.y, fma2v(w01p, Bb.y, mul2(w00p, A.y))));
            ulonglong2 rr; rr.x = r0; rr.y = r1;
            *(ulonglong2*)(xs + px*68 + c4*4) = rr;
        }
        // stage B frags
        {
            const uint4* src = (const uint4*)(g_wt3 + k*4096);
            for (int e = tid; e < 1024; e += 256) bB[e] = src[e];
        }
        __syncthreads();
#pragma unroll
        for (int ks = 0; ks < 8; ks++) {
            int ra = row0*68 + ks*8 + tig;
            uint32_t a0 = __float_as_uint(xs[ra]);
            uint32_t a1 = __float_as_uint(xs[ra + 8*68]);
            uint32_t a2 = __float_as_uint(xs[ra + 4]);
            uint32_t a3 = __float_as_uint(xs[ra + 8*68 + 4]);
#pragma unroll
            for (int j4 = 0; j4 < 4; j4++) {
                uint4 bf = bB[(ks*4 + j4)*32 + lane];
                mma8(acc[j4*2],     a0, a1, a2, a3, bf.x, bf.y);
                mma8(acc[j4*2 + 1], a0, a1, a2, a3, bf.z, bf.w);
            }
        }
        __syncthreads();
    }

    // ---------- Epilogue: NCHW store + bias ----------
#pragma unroll
    for (int j = 0; j < 8; j++) {
        int o = j*8 + tig*2;
        float b0v = __ldg(bias + o);
        float b1v = __ldg(bias + o + 1);
        size_t base0 = (((size_t)b*O_ + o    )*H_ + h)*W_;
        size_t base1 = (((size_t)b*O_ + o + 1)*H_ + h)*W_;
        out[base0 + row0]     = acc[j].x + b0v;
        out[base1 + row0]     = acc[j].y + b1v;
        out[base0 + row0 + 8] = acc[j].z + b0v;
        out[base1 + row0 + 8] = acc[j].w + b1v;
    }
}

extern "C" void kernel_launch(void* const* d_in, const int* in_sizes, int n_in,
                              void* d_out, int out_size) {
    const float* x         = (const float*)d_in[0];
    const float* weight    = (const float*)d_in[1];
    const float* bias      = (const float*)d_in[2];
    const float* om_weight = (const float*)d_in[3];
    const float* om_bias   = (const float*)d_in[4];
    float* out = (float*)d_out;

    int B = in_sizes[0] / (C_*H_*W_);
    if (B < 1) B = 1;
    if (B > Bmax) B = Bmax;

    cudaFuncSetAttribute(k_dcn, cudaFuncAttributeMaxDynamicSharedMemorySize, SM_TOT);

    k_transpose<<<dim3(W_/32, H_, B*2), 256>>>(x);
    int nrep = K_*4096 + K_*2048;
    k_repack<<<(nrep + 255)/256, 256>>>(weight, om_weight);
    k_dcn<<<dim3(H_, B), 256, SM_TOT>>>(bias, om_bias, out);
}